// round 1
// baseline (speedup 1.0000x reference)
#include <cuda_runtime.h>
#include <cuda_bf16.h>

#define B_ 4
#define T_ 2048
#define C_ 2048
#define H_ 32
#define KD_ 64
#define M_ (B_*T_)
#define NTOT (M_*C_)
#define EPS_ 0.00064f
#define PCH 65

// ---------------- scratch (static device globals; allocation-free) ----------------
__device__ float g_xr[NTOT];
__device__ float g_xk[NTOT];
__device__ float g_xv[NTOT];
__device__ float g_xg[NTOT];
__device__ float g_r[NTOT];
__device__ float g_k[NTOT];
__device__ float g_v[NTOT];
__device__ float g_gt[NTOT];
__device__ float g_z[NTOT];

// ---------------- token-shift mixing ----------------
__global__ void mix_kernel(const float* __restrict__ x, const float* __restrict__ state,
                           const float* __restrict__ tmk, const float* __restrict__ tmv,
                           const float* __restrict__ tmr, const float* __restrict__ tmg)
{
    int idx = blockIdx.x * 256 + threadIdx.x;
    if (idx >= NTOT) return;
    int c = idx & (C_ - 1);
    int t = (idx >> 11) & (T_ - 1);
    float xc = x[idx];
    float xp = (t == 0) ? state[c] : x[idx - C_];
    float mk = tmk[c], mv = tmv[c], mr = tmr[c], mg = tmg[c];
    g_xk[idx] = xc * mk + xp * (1.f - mk);
    g_xv[idx] = xc * mv + xp * (1.f - mv);
    g_xr[idx] = xc * mr + xp * (1.f - mr);
    g_xg[idx] = xc * mg + xp * (1.f - mg);
}

// ---------------- fp32 SGEMM: C[m][n] = sum_k A[m][k]*B[n][k]  (A MxK, B NxK row-major) --------
// M=8192, N=K=2048 fixed. ACT=1 -> silu epilogue.
template<int ACT>
__launch_bounds__(256)
__global__ void sgemm_nt(const float* __restrict__ A, const float* __restrict__ Bm,
                         float* __restrict__ C)
{
    const int N = C_, K = C_;
    __shared__ float As[8][128];
    __shared__ float Bs[8][128];
    int tid = threadIdx.x;
    int bm = blockIdx.y * 128, bn = blockIdx.x * 128;
    int lrow = tid >> 1, lcol = (tid & 1) * 4;
    int ty = tid >> 4, tx = tid & 15;

    float acc[8][8];
#pragma unroll
    for (int i = 0; i < 8; i++)
#pragma unroll
        for (int j = 0; j < 8; j++) acc[i][j] = 0.f;

    const float* Ap = A + (bm + lrow) * K + lcol;
    const float* Bp = Bm + (bn + lrow) * K + lcol;

    for (int k0 = 0; k0 < K; k0 += 8) {
        float4 a4 = *(const float4*)(Ap + k0);
        float4 b4 = *(const float4*)(Bp + k0);
        As[lcol + 0][lrow] = a4.x; As[lcol + 1][lrow] = a4.y;
        As[lcol + 2][lrow] = a4.z; As[lcol + 3][lrow] = a4.w;
        Bs[lcol + 0][lrow] = b4.x; Bs[lcol + 1][lrow] = b4.y;
        Bs[lcol + 2][lrow] = b4.z; Bs[lcol + 3][lrow] = b4.w;
        __syncthreads();
#pragma unroll
        for (int kk = 0; kk < 8; kk++) {
            float ar[8], br[8];
#pragma unroll
            for (int i = 0; i < 8; i++) ar[i] = As[kk][ty * 8 + i];
#pragma unroll
            for (int j = 0; j < 8; j++) br[j] = Bs[kk][tx * 8 + j];
#pragma unroll
            for (int i = 0; i < 8; i++)
#pragma unroll
                for (int j = 0; j < 8; j++) acc[i][j] += ar[i] * br[j];
        }
        __syncthreads();
    }

#pragma unroll
    for (int i = 0; i < 8; i++) {
        int r = bm + ty * 8 + i;
#pragma unroll
        for (int j = 0; j < 8; j++) {
            float v = acc[i][j];
            if (ACT == 1) v = v / (1.f + expf(-v));
            C[r * N + bn + tx * 8 + j] = v;
        }
    }
}

// ---------------- wkv chunk-scan + base + bonus + bf16-cast + groupnorm + g-gate -------------
// One block per (b,h). 256 threads: thread = (row = t-local or k-index, jg = 16-col group).
__global__ void wkv_kernel(const float* __restrict__ wkvstate,
                           const float* __restrict__ time_decay,
                           const float* __restrict__ time_faaaa,
                           const float* __restrict__ lnw,
                           const float* __restrict__ lnb)
{
    extern __shared__ float sm[];
    float (*Rs)[PCH] = (float (*)[PCH])(sm);
    float (*Ks)[PCH] = (float (*)[PCH])(sm + 1 * 64 * PCH);
    float (*Vs)[PCH] = (float (*)[PCH])(sm + 2 * 64 * PCH);
    float (*Am)[PCH] = (float (*)[PCH])(sm + 3 * 64 * PCH);
    float (*Ss)[PCH] = (float (*)[PCH])(sm + 4 * 64 * PCH);
    float (*WF)[PCH] = (float (*)[PCH])(sm + 5 * 64 * PCH);
    float (*Ws)[PCH] = (float (*)[PCH])(sm + 6 * 64 * PCH);
    __shared__ float ew[64], uu[64], bonus[64], mu_s[64], rstd_s[64], lw_s[64], lb_s[64];

    int bh = blockIdx.x, b = bh >> 5, h = bh & 31;
    int tid = threadIdx.x;
    int row = tid & 63, jg = tid >> 6, j0 = jg * 16;

    if (tid < 64) {
        ew[tid]   = expf(time_decay[h * 64 + tid]);   // exp(d); w = exp(-ew)
        uu[tid]   = time_faaaa[h * 64 + tid];
        lw_s[tid] = lnw[h * 64 + tid];
        lb_s[tid] = lnb[h * 64 + tid];
    }
    const float* W0 = wkvstate + h * 64 * 64;
#pragma unroll
    for (int j = 0; j < 16; j++) {
        Ss[row][j0 + j] = 0.f;
        Ws[row][j0 + j] = W0[row * 64 + j0 + j];
    }
    __syncthreads();

    const int cbase = (b * T_) * C_ + h * 64;

    for (int ck = 0; ck < 32; ck++) {
        int t0 = ck * 64;
        int off = cbase + (t0 + row) * C_ + j0;

        // load R, K(raw), V tiles (64x64), and WF = r * w^t (global t)
#pragma unroll
        for (int j4 = 0; j4 < 4; j4++) {
            float4 r4 = *(const float4*)&g_r[off + 4 * j4];
            float4 k4 = *(const float4*)&g_k[off + 4 * j4];
            float4 v4 = *(const float4*)&g_v[off + 4 * j4];
            int jj = j0 + 4 * j4;
            Rs[row][jj + 0] = r4.x; Rs[row][jj + 1] = r4.y; Rs[row][jj + 2] = r4.z; Rs[row][jj + 3] = r4.w;
            Ks[row][jj + 0] = k4.x; Ks[row][jj + 1] = k4.y; Ks[row][jj + 2] = k4.z; Ks[row][jj + 3] = k4.w;
            Vs[row][jj + 0] = v4.x; Vs[row][jj + 1] = v4.y; Vs[row][jj + 2] = v4.z; Vs[row][jj + 3] = v4.w;
        }
        float tg = (float)(t0 + row);
#pragma unroll
        for (int j = 0; j < 16; j++)
            WF[row][j0 + j] = Rs[row][j0 + j] * expf(-tg * ew[j0 + j]);
        __syncthreads();

        // bonus[t] = sum_k r*k_raw*u
        if (tid < 64) {
            float s = 0.f;
            for (int kk = 0; kk < 64; kk++) s += Rs[tid][kk] * Ks[tid][kk] * uu[kk];
            bonus[tid] = s;
        }
        __syncthreads();

        // K2[q][c] = k[q][c] * w_c^(T-1-q)   (in place)
        {
            float qb = (float)(T_ - 1 - (t0 + row));
#pragma unroll
            for (int j = 0; j < 16; j++)
                Ks[row][j0 + j] *= expf(-qb * ew[j0 + j]);
        }
        __syncthreads();

        // A = R K2^T, strict lower-triangular mask (q < t)
        {
            float a[16];
#pragma unroll
            for (int j = 0; j < 16; j++) a[j] = 0.f;
            for (int kk = 0; kk < 64; kk++) {
                float rv = Rs[row][kk];
#pragma unroll
                for (int j = 0; j < 16; j++) a[j] += rv * Ks[j0 + j][kk];
            }
#pragma unroll
            for (int j = 0; j < 16; j++)
                Am[row][j0 + j] = (j0 + j < row) ? a[j] : 0.f;
        }
        __syncthreads();

        // O = A V + bonus*v[t] + R S + (r.w^t) W0
        float o[16];
#pragma unroll
        for (int j = 0; j < 16; j++) o[j] = 0.f;
        for (int q = 0; q < 64; q++) {
            float av = Am[row][q];
#pragma unroll
            for (int j = 0; j < 16; j++) o[j] += av * Vs[q][j0 + j];
        }
        {
            float bb = bonus[row];
#pragma unroll
            for (int j = 0; j < 16; j++) o[j] += bb * Vs[row][j0 + j];
        }
        for (int kk = 0; kk < 64; kk++) {
            float rv = Rs[row][kk];
            float rw = WF[row][kk];
#pragma unroll
            for (int j = 0; j < 16; j++)
                o[j] += rv * Ss[kk][j0 + j] + rw * Ws[kk][j0 + j];
        }
        __syncthreads();

        // S += K2^T V   (thread: row = k-index)
        {
            float sa[16];
#pragma unroll
            for (int j = 0; j < 16; j++) sa[j] = 0.f;
            for (int q = 0; q < 64; q++) {
                float kv = Ks[q][row];
#pragma unroll
                for (int j = 0; j < 16; j++) sa[j] += kv * Vs[q][j0 + j];
            }
#pragma unroll
            for (int j = 0; j < 16; j++) Ss[row][j0 + j] += sa[j];
        }

        // y = bf16-cast, stash in Am for per-row groupnorm
#pragma unroll
        for (int j = 0; j < 16; j++)
            Am[row][j0 + j] = __bfloat162float(__float2bfloat16(o[j]));
        __syncthreads();

        if (tid < 64) {
            float m = 0.f;
            for (int j = 0; j < 64; j++) m += Am[tid][j];
            m *= (1.f / 64.f);
            float v2 = 0.f;
            for (int j = 0; j < 64; j++) { float d = Am[tid][j] - m; v2 += d * d; }
            v2 *= (1.f / 64.f);
            mu_s[tid] = m;
            rstd_s[tid] = 1.f / sqrtf(v2 + EPS_);
        }
        __syncthreads();

        {
            float m = mu_s[row], rs = rstd_s[row];
#pragma unroll
            for (int j = 0; j < 16; j++) {
                float y = (Am[row][j0 + j] - m) * rs * lw_s[j0 + j] + lb_s[j0 + j];
                g_z[off + j] = y * g_gt[off + j];
            }
        }
        __syncthreads();
    }
}

// ---------------- launch ----------------
extern "C" void kernel_launch(void* const* d_in, const int* in_sizes, int n_in,
                              void* d_out, int out_size)
{
    const float* x     = (const float*)d_in[0];
    const float* state = (const float*)d_in[1];
    const float* wkvs  = (const float*)d_in[2];
    const float* tmk   = (const float*)d_in[3];
    const float* tmv   = (const float*)d_in[4];
    const float* tmr   = (const float*)d_in[5];
    const float* tmg   = (const float*)d_in[6];
    const float* tdec  = (const float*)d_in[7];
    const float* tfaa  = (const float*)d_in[8];
    const float* w_r   = (const float*)d_in[9];
    const float* w_k   = (const float*)d_in[10];
    const float* w_v   = (const float*)d_in[11];
    const float* w_g   = (const float*)d_in[12];
    const float* w_o   = (const float*)d_in[13];
    const float* lnw   = (const float*)d_in[14];
    const float* lnb   = (const float*)d_in[15];

    float *p_xr, *p_xk, *p_xv, *p_xg, *p_r, *p_k, *p_v, *p_g, *p_z;
    cudaGetSymbolAddress((void**)&p_xr, g_xr);
    cudaGetSymbolAddress((void**)&p_xk, g_xk);
    cudaGetSymbolAddress((void**)&p_xv, g_xv);
    cudaGetSymbolAddress((void**)&p_xg, g_xg);
    cudaGetSymbolAddress((void**)&p_r,  g_r);
    cudaGetSymbolAddress((void**)&p_k,  g_k);
    cudaGetSymbolAddress((void**)&p_v,  g_v);
    cudaGetSymbolAddress((void**)&p_g,  g_gt);
    cudaGetSymbolAddress((void**)&p_z,  g_z);

    mix_kernel<<<(NTOT + 255) / 256, 256>>>(x, state, tmk, tmv, tmr, tmg);

    dim3 gg(C_ / 128, M_ / 128);
    sgemm_nt<0><<<gg, 256>>>(p_xr, w_r, p_r);
    sgemm_nt<0><<<gg, 256>>>(p_xk, w_k, p_k);
    sgemm_nt<0><<<gg, 256>>>(p_xv, w_v, p_v);
    sgemm_nt<1><<<gg, 256>>>(p_xg, w_g, p_g);

    int smbytes = 7 * 64 * PCH * 4;
    cudaFuncSetAttribute(wkv_kernel, cudaFuncAttributeMaxDynamicSharedMemorySize, smbytes);
    wkv_kernel<<<B_ * H_, 256, smbytes>>>(wkvs, tdec, tfaa, lnw, lnb);

    sgemm_nt<0><<<gg, 256>>>(p_z, w_o, (float*)d_out);
}

// round 4
// speedup vs baseline: 2.7080x; 2.7080x over previous
#include <cuda_runtime.h>
#include <cuda_bf16.h>
#include <cstdint>

#define B_ 4
#define T_ 2048
#define C_ 2048
#define H_ 32
#define M_ (B_*T_)
#define NTOT (M_*C_)
#define WSZ (C_*C_)
#define EPS_ 0.00064f
#define PCH 65

// ---------------- scratch (static device globals; allocation-free) ----------------
__device__ __nv_bfloat16 g_xrh[NTOT], g_xrl[NTOT];
__device__ __nv_bfloat16 g_xkh[NTOT], g_xkl[NTOT];
__device__ __nv_bfloat16 g_xvh[NTOT], g_xvl[NTOT];
__device__ __nv_bfloat16 g_xgh[NTOT], g_xgl[NTOT];
__device__ __nv_bfloat16 g_zh[NTOT],  g_zl[NTOT];
__device__ float g_r[NTOT], g_k[NTOT], g_v[NTOT], g_gt[NTOT];
__device__ __nv_bfloat16 g_wrh[WSZ], g_wrl[WSZ];
__device__ __nv_bfloat16 g_wkh[WSZ], g_wkl[WSZ];
__device__ __nv_bfloat16 g_wvh[WSZ], g_wvl[WSZ];
__device__ __nv_bfloat16 g_wgh[WSZ], g_wgl[WSZ];
__device__ __nv_bfloat16 g_woh[WSZ], g_wol[WSZ];

// ---------------- PTX helpers (all baseline PTX, no sm_103a-only features) ----------------
__device__ __forceinline__ uint32_t smem_u32(const void* p) {
    uint32_t a;
    asm("{ .reg .u64 t; cvta.to.shared.u64 t, %1; cvt.u32.u64 %0, t; }" : "=r"(a) : "l"(p));
    return a;
}
#define CPASYNC16(dst, src) \
    asm volatile("cp.async.cg.shared.global [%0], [%1], 16;" :: "r"(dst), "l"(src))
#define CPCOMMIT() asm volatile("cp.async.commit_group;" ::: "memory")
#define CPWAIT1()  asm volatile("cp.async.wait_group 1;" ::: "memory")
#define CPWAIT0()  asm volatile("cp.async.wait_group 0;" ::: "memory")

__device__ __forceinline__ void ldsm_x4(uint32_t* r, uint32_t addr) {
    asm volatile("ldmatrix.sync.aligned.m8n8.x4.shared.b16 {%0,%1,%2,%3}, [%4];"
                 : "=r"(r[0]), "=r"(r[1]), "=r"(r[2]), "=r"(r[3]) : "r"(addr));
}
__device__ __forceinline__ void mma_bf16(float* c, const uint32_t* a, const uint32_t* b) {
    asm volatile(
        "mma.sync.aligned.m16n8k16.row.col.f32.bf16.bf16.f32 "
        "{%0,%1,%2,%3}, {%4,%5,%6,%7}, {%8,%9}, {%0,%1,%2,%3};"
        : "+f"(c[0]), "+f"(c[1]), "+f"(c[2]), "+f"(c[3])
        : "r"(a[0]), "r"(a[1]), "r"(a[2]), "r"(a[3]), "r"(b[0]), "r"(b[1]));
}

// smem tile layout: 128 rows x 32 bf16 cols = row stride 64B; 16B chunks swizzled
__device__ __forceinline__ uint32_t swz(uint32_t row, uint32_t kc) {
    return row * 64 + ((kc ^ ((row >> 1) & 3)) * 16);
}

// ---------------- token-shift mixing -> split bf16 ----------------
__global__ void mix_kernel(const float* __restrict__ x, const float* __restrict__ state,
                           const float* __restrict__ tmk, const float* __restrict__ tmv,
                           const float* __restrict__ tmr, const float* __restrict__ tmg)
{
    int idx = blockIdx.x * 256 + threadIdx.x;
    if (idx >= NTOT) return;
    int c = idx & (C_ - 1);
    int t = (idx >> 11) & (T_ - 1);
    float xc = x[idx];
    float xp = (t == 0) ? state[c] : x[idx - C_];
    float mk = tmk[c], mv = tmv[c], mr = tmr[c], mg = tmg[c];
    float vk = xc * mk + xp * (1.f - mk);
    float vv = xc * mv + xp * (1.f - mv);
    float vr = xc * mr + xp * (1.f - mr);
    float vg = xc * mg + xp * (1.f - mg);
    __nv_bfloat16 h;
    h = __float2bfloat16(vk); g_xkh[idx] = h; g_xkl[idx] = __float2bfloat16(vk - __bfloat162float(h));
    h = __float2bfloat16(vv); g_xvh[idx] = h; g_xvl[idx] = __float2bfloat16(vv - __bfloat162float(h));
    h = __float2bfloat16(vr); g_xrh[idx] = h; g_xrl[idx] = __float2bfloat16(vr - __bfloat162float(h));
    h = __float2bfloat16(vg); g_xgh[idx] = h; g_xgl[idx] = __float2bfloat16(vg - __bfloat162float(h));
}

// ---------------- fp32 -> split bf16 weight conversion ----------------
__global__ void wconv_kernel(const float* __restrict__ w, __nv_bfloat16* __restrict__ wh,
                             __nv_bfloat16* __restrict__ wl)
{
    int idx = blockIdx.x * 256 + threadIdx.x;
    if (idx >= WSZ) return;
    float v = w[idx];
    __nv_bfloat16 h = __float2bfloat16(v);
    wh[idx] = h;
    wl[idx] = __float2bfloat16(v - __bfloat162float(h));
}

// ---------------- HMMA split-bf16 GEMM: C[m][n] = sum_k A[m][k]*B[n][k] ------------
// CTA tile 128x128, BK=32, 3-stage cp.async pipeline, 8 warps (4m x 2n), warp tile 32x64.
#define NSTAGE 3
#define STG_BYTES 32768    /* 4 tiles x 8KB */
template<int ACT>
__launch_bounds__(256)
__global__ void hgemm_nt(const __nv_bfloat16* __restrict__ Ah, const __nv_bfloat16* __restrict__ Al,
                         const __nv_bfloat16* __restrict__ Bh, const __nv_bfloat16* __restrict__ Bl,
                         float* __restrict__ Cmat)
{
    extern __shared__ __align__(128) char smem[];
    const uint32_t sb = smem_u32(smem);
    const int tid = threadIdx.x;
    const int wid = tid >> 5;
    const int lid = tid & 31;
    const int warp_m = wid >> 1;      // 0..3 -> rows warp_m*32
    const int warp_n = wid & 1;       // 0..1 -> cols warp_n*64
    const int bm = blockIdx.y * 128, bn = blockIdx.x * 128;

    const __nv_bfloat16* mats[4] = { Ah, Al, Bh, Bl };
    const int rbase[4] = { bm, bm, bn, bn };

    // per-thread load coords (2 chunks of 16B per tile per stage)
    const int chunk0 = tid, chunk1 = tid + 256;
    const int lrow0 = chunk0 >> 2, lkc0 = chunk0 & 3;
    const int lrow1 = chunk1 >> 2, lkc1 = chunk1 & 3;

    auto load_stage = [&](int s, int p) {
        const int k0 = s * 32;
        const uint32_t sbase = sb + p * STG_BYTES;
#pragma unroll
        for (int m = 0; m < 4; m++) {
            const __nv_bfloat16* src = mats[m] + (size_t)rbase[m] * C_ + k0;
            const uint32_t tb = sbase + m * 8192;
            CPASYNC16(tb + swz(lrow0, lkc0), (const char*)(src + lrow0 * C_) + lkc0 * 16);
            CPASYNC16(tb + swz(lrow1, lkc1), (const char*)(src + lrow1 * C_) + lkc1 * 16);
        }
    };

    float acc[2][8][4];
#pragma unroll
    for (int mb = 0; mb < 2; mb++)
#pragma unroll
        for (int nf = 0; nf < 8; nf++)
#pragma unroll
            for (int q = 0; q < 4; q++) acc[mb][nf][q] = 0.f;

    load_stage(0, 0); CPCOMMIT();
    load_stage(1, 1); CPCOMMIT();

    const int KS = C_ / 32;  // 64
    // precompute ldmatrix lane coords
    const uint32_t a_row = (lid & 7) + ((lid >> 3) & 1) * 8;       // within 16-row block
    const uint32_t a_kc  = (lid >> 4);                              // 0/1 (chunk within k16)
    const uint32_t b_row = (lid & 7) + ((lid >> 4) & 1) * 8;
    const uint32_t b_kc  = (lid >> 3) & 1;

    for (int ks = 0; ks < KS; ks++) {
        CPWAIT1();
        __syncthreads();
        if (ks + 2 < KS) load_stage(ks + 2, (ks + 2) % NSTAGE);
        CPCOMMIT();

        const uint32_t sbase = sb + (ks % NSTAGE) * STG_BYTES;
#pragma unroll
        for (int kk = 0; kk < 2; kk++) {
            uint32_t ah[2][4], al[2][4];
#pragma unroll
            for (int mb = 0; mb < 2; mb++) {
                uint32_t row = warp_m * 32 + mb * 16 + a_row;
                uint32_t off = swz(row, kk * 2 + a_kc);
                ldsm_x4(ah[mb], sbase + 0 * 8192 + off);
                ldsm_x4(al[mb], sbase + 1 * 8192 + off);
            }
            uint32_t bh[8][2], bl[8][2];
#pragma unroll
            for (int nb = 0; nb < 4; nb++) {
                uint32_t row = warp_n * 64 + nb * 16 + b_row;
                uint32_t off = swz(row, kk * 2 + b_kc);
                uint32_t t[4];
                ldsm_x4(t, sbase + 2 * 8192 + off);
                bh[nb * 2][0] = t[0]; bh[nb * 2][1] = t[1];
                bh[nb * 2 + 1][0] = t[2]; bh[nb * 2 + 1][1] = t[3];
                ldsm_x4(t, sbase + 3 * 8192 + off);
                bl[nb * 2][0] = t[0]; bl[nb * 2][1] = t[1];
                bl[nb * 2 + 1][0] = t[2]; bl[nb * 2 + 1][1] = t[3];
            }
#pragma unroll
            for (int mb = 0; mb < 2; mb++)
#pragma unroll
                for (int nf = 0; nf < 8; nf++) {
                    mma_bf16(acc[mb][nf], ah[mb], bh[nf]);
                    mma_bf16(acc[mb][nf], ah[mb], bl[nf]);
                    mma_bf16(acc[mb][nf], al[mb], bh[nf]);
                }
        }
    }
    CPWAIT0();

    // ---- epilogue ----
#pragma unroll
    for (int mb = 0; mb < 2; mb++) {
        int r0 = bm + warp_m * 32 + mb * 16 + (lid >> 2);
#pragma unroll
        for (int nf = 0; nf < 8; nf++) {
            int cc = bn + warp_n * 64 + nf * 8 + (lid & 3) * 2;
            float v0 = acc[mb][nf][0], v1 = acc[mb][nf][1];
            float v2 = acc[mb][nf][2], v3 = acc[mb][nf][3];
            if (ACT == 1) {
                v0 = v0 / (1.f + expf(-v0)); v1 = v1 / (1.f + expf(-v1));
                v2 = v2 / (1.f + expf(-v2)); v3 = v3 / (1.f + expf(-v3));
            }
            float2 p0 = make_float2(v0, v1), p1 = make_float2(v2, v3);
            *(float2*)&Cmat[(size_t)r0 * C_ + cc] = p0;
            *(float2*)&Cmat[(size_t)(r0 + 8) * C_ + cc] = p1;
        }
    }
}

// ---------------- wkv chunk-scan + base + bonus + bf16-cast + groupnorm + g-gate -------------
__global__ void wkv_kernel(const float* __restrict__ wkvstate,
                           const float* __restrict__ time_decay,
                           const float* __restrict__ time_faaaa,
                           const float* __restrict__ lnw,
                           const float* __restrict__ lnb)
{
    extern __shared__ float sm[];
    float (*Rs)[PCH] = (float (*)[PCH])(sm);
    float (*Ks)[PCH] = (float (*)[PCH])(sm + 1 * 64 * PCH);
    float (*Vs)[PCH] = (float (*)[PCH])(sm + 2 * 64 * PCH);
    float (*Am)[PCH] = (float (*)[PCH])(sm + 3 * 64 * PCH);
    float (*Ss)[PCH] = (float (*)[PCH])(sm + 4 * 64 * PCH);
    float (*WF)[PCH] = (float (*)[PCH])(sm + 5 * 64 * PCH);
    float (*Ws)[PCH] = (float (*)[PCH])(sm + 6 * 64 * PCH);
    __shared__ float ew[64], uu[64], bonus[64], mu_s[64], rstd_s[64], lw_s[64], lb_s[64];

    int bh = blockIdx.x, b = bh >> 5, h = bh & 31;
    int tid = threadIdx.x;
    int row = tid & 63, jg = tid >> 6, j0 = jg * 16;

    if (tid < 64) {
        ew[tid]   = expf(time_decay[h * 64 + tid]);
        uu[tid]   = time_faaaa[h * 64 + tid];
        lw_s[tid] = lnw[h * 64 + tid];
        lb_s[tid] = lnb[h * 64 + tid];
    }
    const float* W0 = wkvstate + h * 64 * 64;
#pragma unroll
    for (int j = 0; j < 16; j++) {
        Ss[row][j0 + j] = 0.f;
        Ws[row][j0 + j] = W0[row * 64 + j0 + j];
    }
    __syncthreads();

    const int cbase = (b * T_) * C_ + h * 64;

    for (int ck = 0; ck < 32; ck++) {
        int t0 = ck * 64;
        int off = cbase + (t0 + row) * C_ + j0;

#pragma unroll
        for (int j4 = 0; j4 < 4; j4++) {
            float4 r4 = *(const float4*)&g_r[off + 4 * j4];
            float4 k4 = *(const float4*)&g_k[off + 4 * j4];
            float4 v4 = *(const float4*)&g_v[off + 4 * j4];
            int jj = j0 + 4 * j4;
            Rs[row][jj + 0] = r4.x; Rs[row][jj + 1] = r4.y; Rs[row][jj + 2] = r4.z; Rs[row][jj + 3] = r4.w;
            Ks[row][jj + 0] = k4.x; Ks[row][jj + 1] = k4.y; Ks[row][jj + 2] = k4.z; Ks[row][jj + 3] = k4.w;
            Vs[row][jj + 0] = v4.x; Vs[row][jj + 1] = v4.y; Vs[row][jj + 2] = v4.z; Vs[row][jj + 3] = v4.w;
        }
        float tg = (float)(t0 + row);
#pragma unroll
        for (int j = 0; j < 16; j++)
            WF[row][j0 + j] = Rs[row][j0 + j] * expf(-tg * ew[j0 + j]);
        __syncthreads();

        if (tid < 64) {
            float s = 0.f;
            for (int kk = 0; kk < 64; kk++) s += Rs[tid][kk] * Ks[tid][kk] * uu[kk];
            bonus[tid] = s;
        }
        __syncthreads();

        {
            float qb = (float)(T_ - 1 - (t0 + row));
#pragma unroll
            for (int j = 0; j < 16; j++)
                Ks[row][j0 + j] *= expf(-qb * ew[j0 + j]);
        }
        __syncthreads();

        {
            float a[16];
#pragma unroll
            for (int j = 0; j < 16; j++) a[j] = 0.f;
            for (int kk = 0; kk < 64; kk++) {
                float rv = Rs[row][kk];
#pragma unroll
                for (int j = 0; j < 16; j++) a[j] += rv * Ks[j0 + j][kk];
            }
#pragma unroll
            for (int j = 0; j < 16; j++)
                Am[row][j0 + j] = (j0 + j < row) ? a[j] : 0.f;
        }
        __syncthreads();

        float o[16];
#pragma unroll
        for (int j = 0; j < 16; j++) o[j] = 0.f;
        for (int q = 0; q < 64; q++) {
            float av = Am[row][q];
#pragma unroll
            for (int j = 0; j < 16; j++) o[j] += av * Vs[q][j0 + j];
        }
        {
            float bb = bonus[row];
#pragma unroll
            for (int j = 0; j < 16; j++) o[j] += bb * Vs[row][j0 + j];
        }
        for (int kk = 0; kk < 64; kk++) {
            float rv = Rs[row][kk];
            float rw = WF[row][kk];
#pragma unroll
            for (int j = 0; j < 16; j++)
                o[j] += rv * Ss[kk][j0 + j] + rw * Ws[kk][j0 + j];
        }
        __syncthreads();

        {
            float sa[16];
#pragma unroll
            for (int j = 0; j < 16; j++) sa[j] = 0.f;
            for (int q = 0; q < 64; q++) {
                float kv = Ks[q][row];
#pragma unroll
                for (int j = 0; j < 16; j++) sa[j] += kv * Vs[q][j0 + j];
            }
#pragma unroll
            for (int j = 0; j < 16; j++) Ss[row][j0 + j] += sa[j];
        }

#pragma unroll
        for (int j = 0; j < 16; j++)
            Am[row][j0 + j] = __bfloat162float(__float2bfloat16(o[j]));
        __syncthreads();

        if (tid < 64) {
            float m = 0.f;
            for (int j = 0; j < 64; j++) m += Am[tid][j];
            m *= (1.f / 64.f);
            float v2 = 0.f;
            for (int j = 0; j < 64; j++) { float d = Am[tid][j] - m; v2 += d * d; }
            v2 *= (1.f / 64.f);
            mu_s[tid] = m;
            rstd_s[tid] = 1.f / sqrtf(v2 + EPS_);
        }
        __syncthreads();

        {
            float m = mu_s[row], rs = rstd_s[row];
#pragma unroll
            for (int j = 0; j < 16; j++) {
                float y = (Am[row][j0 + j] - m) * rs * lw_s[j0 + j] + lb_s[j0 + j];
                float z = y * g_gt[off + j];
                __nv_bfloat16 hh = __float2bfloat16(z);
                g_zh[off + j] = hh;
                g_zl[off + j] = __float2bfloat16(z - __bfloat162float(hh));
            }
        }
        __syncthreads();
    }
}

// ---------------- launch ----------------
extern "C" void kernel_launch(void* const* d_in, const int* in_sizes, int n_in,
                              void* d_out, int out_size)
{
    const float* x     = (const float*)d_in[0];
    const float* state = (const float*)d_in[1];
    const float* wkvs  = (const float*)d_in[2];
    const float* tmk   = (const float*)d_in[3];
    const float* tmv   = (const float*)d_in[4];
    const float* tmr   = (const float*)d_in[5];
    const float* tmg   = (const float*)d_in[6];
    const float* tdec  = (const float*)d_in[7];
    const float* tfaa  = (const float*)d_in[8];
    const float* w_r   = (const float*)d_in[9];
    const float* w_k   = (const float*)d_in[10];
    const float* w_v   = (const float*)d_in[11];
    const float* w_g   = (const float*)d_in[12];
    const float* w_o   = (const float*)d_in[13];
    const float* lnw   = (const float*)d_in[14];
    const float* lnb   = (const float*)d_in[15];

    __nv_bfloat16 *xrh,*xrl,*xkh,*xkl,*xvh,*xvl,*xgh,*xgl,*zh,*zl;
    __nv_bfloat16 *wrh,*wrl,*wkh,*wkl,*wvh,*wvl,*wgh,*wgl,*woh,*wol;
    float *pr,*pk,*pv,*pg;
    cudaGetSymbolAddress((void**)&xrh, g_xrh); cudaGetSymbolAddress((void**)&xrl, g_xrl);
    cudaGetSymbolAddress((void**)&xkh, g_xkh); cudaGetSymbolAddress((void**)&xkl, g_xkl);
    cudaGetSymbolAddress((void**)&xvh, g_xvh); cudaGetSymbolAddress((void**)&xvl, g_xvl);
    cudaGetSymbolAddress((void**)&xgh, g_xgh); cudaGetSymbolAddress((void**)&xgl, g_xgl);
    cudaGetSymbolAddress((void**)&zh,  g_zh);  cudaGetSymbolAddress((void**)&zl,  g_zl);
    cudaGetSymbolAddress((void**)&wrh, g_wrh); cudaGetSymbolAddress((void**)&wrl, g_wrl);
    cudaGetSymbolAddress((void**)&wkh, g_wkh); cudaGetSymbolAddress((void**)&wkl, g_wkl);
    cudaGetSymbolAddress((void**)&wvh, g_wvh); cudaGetSymbolAddress((void**)&wvl, g_wvl);
    cudaGetSymbolAddress((void**)&wgh, g_wgh); cudaGetSymbolAddress((void**)&wgl, g_wgl);
    cudaGetSymbolAddress((void**)&woh, g_woh); cudaGetSymbolAddress((void**)&wol, g_wol);
    cudaGetSymbolAddress((void**)&pr,  g_r);   cudaGetSymbolAddress((void**)&pk,  g_k);
    cudaGetSymbolAddress((void**)&pv,  g_v);   cudaGetSymbolAddress((void**)&pg,  g_gt);

    mix_kernel<<<(NTOT + 255) / 256, 256>>>(x, state, tmk, tmv, tmr, tmg);
    int wg = (WSZ + 255) / 256;
    wconv_kernel<<<wg, 256>>>(w_r, wrh, wrl);
    wconv_kernel<<<wg, 256>>>(w_k, wkh, wkl);
    wconv_kernel<<<wg, 256>>>(w_v, wvh, wvl);
    wconv_kernel<<<wg, 256>>>(w_g, wgh, wgl);
    wconv_kernel<<<wg, 256>>>(w_o, woh, wol);

    const int gsm = NSTAGE * STG_BYTES;  // 96KB
    cudaFuncSetAttribute(hgemm_nt<0>, cudaFuncAttributeMaxDynamicSharedMemorySize, gsm);
    cudaFuncSetAttribute(hgemm_nt<1>, cudaFuncAttributeMaxDynamicSharedMemorySize, gsm);

    dim3 gg(C_ / 128, M_ / 128);
    hgemm_nt<0><<<gg, 256, gsm>>>(xrh, xrl, wrh, wrl, pr);
    hgemm_nt<0><<<gg, 256, gsm>>>(xkh, xkl, wkh, wkl, pk);
    hgemm_nt<0><<<gg, 256, gsm>>>(xvh, xvl, wvh, wvl, pv);
    hgemm_nt<1><<<gg, 256, gsm>>>(xgh, xgl, wgh, wgl, pg);

    int smbytes = 7 * 64 * PCH * 4;
    cudaFuncSetAttribute(wkv_kernel, cudaFuncAttributeMaxDynamicSharedMemorySize, smbytes);
    wkv_kernel<<<B_ * H_, 256, smbytes>>>(wkvs, tdec, tfaa, lnw, lnb);

    hgemm_nt<0><<<gg, 256, gsm>>>(zh, zl, woh, wol, (float*)d_out);
}

// round 7
// speedup vs baseline: 2.8108x; 1.0379x over previous
#include <cuda_runtime.h>
#include <cuda_bf16.h>
#include <cstdint>

#define B_ 4
#define T_ 2048
#define C_ 2048
#define H_ 32
#define M_ (B_*T_)
#define NTOT (M_*C_)
#define WSZ (C_*C_)
#define EPS_ 0.00064f
#define PCH 65

// ---------------- scratch (static device globals; allocation-free) ----------------
__device__ __nv_bfloat16 g_xrh[NTOT], g_xrl[NTOT];
__device__ __nv_bfloat16 g_xkh[NTOT], g_xkl[NTOT];
__device__ __nv_bfloat16 g_xvh[NTOT], g_xvl[NTOT];
__device__ __nv_bfloat16 g_xgh[NTOT], g_xgl[NTOT];
__device__ __nv_bfloat16 g_zh[NTOT],  g_zl[NTOT];
__device__ float g_r[NTOT], g_k[NTOT], g_v[NTOT], g_gt[NTOT];
__device__ float g_S[128 * 32 * 4096];   // per-chunk state increments -> exclusive prefix
__device__ float g_po[128 * 32 * 4096];  // chunk-local partial outputs
__device__ __nv_bfloat16 g_wrh[WSZ], g_wrl[WSZ];
__device__ __nv_bfloat16 g_wkh[WSZ], g_wkl[WSZ];
__device__ __nv_bfloat16 g_wvh[WSZ], g_wvl[WSZ];
__device__ __nv_bfloat16 g_wgh[WSZ], g_wgl[WSZ];
__device__ __nv_bfloat16 g_woh[WSZ], g_wol[WSZ];

// ---------------- PTX helpers (baseline PTX only) ----------------
__device__ __forceinline__ uint32_t smem_u32(const void* p) {
    uint32_t a;
    asm("{ .reg .u64 t; cvta.to.shared.u64 t, %1; cvt.u32.u64 %0, t; }" : "=r"(a) : "l"(p));
    return a;
}
#define CPASYNC16(dst, src) \
    asm volatile("cp.async.cg.shared.global [%0], [%1], 16;" :: "r"(dst), "l"(src))
#define CPCOMMIT() asm volatile("cp.async.commit_group;" ::: "memory")
#define CPWAIT1()  asm volatile("cp.async.wait_group 1;" ::: "memory")
#define CPWAIT0()  asm volatile("cp.async.wait_group 0;" ::: "memory")

__device__ __forceinline__ void ldsm_x4(uint32_t* r, uint32_t addr) {
    asm volatile("ldmatrix.sync.aligned.m8n8.x4.shared.b16 {%0,%1,%2,%3}, [%4];"
                 : "=r"(r[0]), "=r"(r[1]), "=r"(r[2]), "=r"(r[3]) : "r"(addr));
}
__device__ __forceinline__ void mma_bf16(float* c, const uint32_t* a, const uint32_t* b) {
    asm volatile(
        "mma.sync.aligned.m16n8k16.row.col.f32.bf16.bf16.f32 "
        "{%0,%1,%2,%3}, {%4,%5,%6,%7}, {%8,%9}, {%0,%1,%2,%3};"
        : "+f"(c[0]), "+f"(c[1]), "+f"(c[2]), "+f"(c[3])
        : "r"(a[0]), "r"(a[1]), "r"(a[2]), "r"(a[3]), "r"(b[0]), "r"(b[1]));
}

// smem tile: 128 rows x 64 bf16 = 128B/row; 8 chunks of 16B, XOR-swizzled
__device__ __forceinline__ uint32_t swz64(uint32_t row, uint32_t kc) {
    return row * 128 + ((kc ^ (row & 7)) * 16);
}

// ---------------- token-shift mixing -> split bf16 ----------------
__global__ void mix_kernel(const float* __restrict__ x, const float* __restrict__ state,
                           const float* __restrict__ tmk, const float* __restrict__ tmv,
                           const float* __restrict__ tmr, const float* __restrict__ tmg)
{
    int idx = blockIdx.x * 256 + threadIdx.x;
    if (idx >= NTOT) return;
    int c = idx & (C_ - 1);
    int t = (idx >> 11) & (T_ - 1);
    float xc = x[idx];
    float xp = (t == 0) ? state[c] : x[idx - C_];
    float mk = tmk[c], mv = tmv[c], mr = tmr[c], mg = tmg[c];
    float vk = xc * mk + xp * (1.f - mk);
    float vv = xc * mv + xp * (1.f - mv);
    float vr = xc * mr + xp * (1.f - mr);
    float vg = xc * mg + xp * (1.f - mg);
    __nv_bfloat16 h;
    h = __float2bfloat16(vk); g_xkh[idx] = h; g_xkl[idx] = __float2bfloat16(vk - __bfloat162float(h));
    h = __float2bfloat16(vv); g_xvh[idx] = h; g_xvl[idx] = __float2bfloat16(vv - __bfloat162float(h));
    h = __float2bfloat16(vr); g_xrh[idx] = h; g_xrl[idx] = __float2bfloat16(vr - __bfloat162float(h));
    h = __float2bfloat16(vg); g_xgh[idx] = h; g_xgl[idx] = __float2bfloat16(vg - __bfloat162float(h));
}

// ---------------- fp32 -> split bf16 weight conversion ----------------
__global__ void wconv_kernel(const float* __restrict__ w, __nv_bfloat16* __restrict__ wh,
                             __nv_bfloat16* __restrict__ wl)
{
    int idx = blockIdx.x * 256 + threadIdx.x;
    if (idx >= WSZ) return;
    float v = w[idx];
    __nv_bfloat16 h = __float2bfloat16(v);
    wh[idx] = h;
    wl[idx] = __float2bfloat16(v - __bfloat162float(h));
}

// ---------------- HMMA split-bf16 GEMM: C[m][n] = sum_k A[m][k]*B[n][k] ------------
// CTA tile 128x128, BK=64, 3-stage cp.async pipeline, 8 warps (4m x 2n), warp tile 32x64.
#define NSTAGE 3
#define STG_BYTES 65536    /* 4 tiles x 16KB */
template<int ACT>
__launch_bounds__(256)
__global__ void hgemm_nt(const __nv_bfloat16* __restrict__ Ah, const __nv_bfloat16* __restrict__ Al,
                         const __nv_bfloat16* __restrict__ Bh, const __nv_bfloat16* __restrict__ Bl,
                         float* __restrict__ Cmat)
{
    extern __shared__ __align__(128) char smem[];
    const uint32_t sb = smem_u32(smem);
    const int tid = threadIdx.x;
    const int wid = tid >> 5;
    const int lid = tid & 31;
    const int warp_m = wid >> 1;
    const int warp_n = wid & 1;
    const int bm = blockIdx.y * 128, bn = blockIdx.x * 128;

    const __nv_bfloat16* mats[4] = { Ah, Al, Bh, Bl };
    const int rbase[4] = { bm, bm, bn, bn };

    auto load_stage = [&](int s, int p) {
        const int k0 = s * 64;
        const uint32_t sbase = sb + p * STG_BYTES;
#pragma unroll
        for (int m = 0; m < 4; m++) {
            const __nv_bfloat16* src = mats[m] + (size_t)rbase[m] * C_ + k0;
            const uint32_t tb = sbase + m * 16384;
#pragma unroll
            for (int i = 0; i < 4; i++) {
                int chunk = tid + 256 * i;
                int row = chunk >> 3, kc = chunk & 7;
                CPASYNC16(tb + swz64(row, kc), (const char*)(src + (size_t)row * C_) + kc * 16);
            }
        }
    };

    float acc[2][8][4];
#pragma unroll
    for (int mb = 0; mb < 2; mb++)
#pragma unroll
        for (int nf = 0; nf < 8; nf++)
#pragma unroll
            for (int q = 0; q < 4; q++) acc[mb][nf][q] = 0.f;

    load_stage(0, 0); CPCOMMIT();
    load_stage(1, 1); CPCOMMIT();

    const int KS = C_ / 64;  // 32
    const uint32_t a_row = lid & 15;
    const uint32_t a_kc  = lid >> 4;
    const uint32_t b_row = (lid & 7) + ((lid >> 4) & 1) * 8;
    const uint32_t b_kc  = (lid >> 3) & 1;

    for (int ks = 0; ks < KS; ks++) {
        CPWAIT1();
        __syncthreads();
        if (ks + 2 < KS) load_stage(ks + 2, (ks + 2) % NSTAGE);
        CPCOMMIT();

        const uint32_t sbase = sb + (ks % NSTAGE) * STG_BYTES;
#pragma unroll
        for (int kk = 0; kk < 4; kk++) {
            uint32_t ah[2][4], al[2][4];
#pragma unroll
            for (int mb = 0; mb < 2; mb++) {
                uint32_t row = warp_m * 32 + mb * 16 + a_row;
                uint32_t off = swz64(row, kk * 2 + a_kc);
                ldsm_x4(ah[mb], sbase + 0 * 16384 + off);
                ldsm_x4(al[mb], sbase + 1 * 16384 + off);
            }
            uint32_t bh[8][2], bl[8][2];
#pragma unroll
            for (int nb = 0; nb < 4; nb++) {
                uint32_t row = warp_n * 64 + nb * 16 + b_row;
                uint32_t off = swz64(row, kk * 2 + b_kc);
                uint32_t t[4];
                ldsm_x4(t, sbase + 2 * 16384 + off);
                bh[nb * 2][0] = t[0]; bh[nb * 2][1] = t[1];
                bh[nb * 2 + 1][0] = t[2]; bh[nb * 2 + 1][1] = t[3];
                ldsm_x4(t, sbase + 3 * 16384 + off);
                bl[nb * 2][0] = t[0]; bl[nb * 2][1] = t[1];
                bl[nb * 2 + 1][0] = t[2]; bl[nb * 2 + 1][1] = t[3];
            }
#pragma unroll
            for (int mb = 0; mb < 2; mb++)
#pragma unroll
                for (int nf = 0; nf < 8; nf++) {
                    mma_bf16(acc[mb][nf], ah[mb], bh[nf]);
                    mma_bf16(acc[mb][nf], ah[mb], bl[nf]);
                    mma_bf16(acc[mb][nf], al[mb], bh[nf]);
                }
        }
    }
    CPWAIT0();

    // ---- epilogue ----
#pragma unroll
    for (int mb = 0; mb < 2; mb++) {
        int r0 = bm + warp_m * 32 + mb * 16 + (lid >> 2);
#pragma unroll
        for (int nf = 0; nf < 8; nf++) {
            int cc = bn + warp_n * 64 + nf * 8 + (lid & 3) * 2;
            float v0 = acc[mb][nf][0], v1 = acc[mb][nf][1];
            float v2 = acc[mb][nf][2], v3 = acc[mb][nf][3];
            if (ACT == 1) {
                v0 = v0 / (1.f + expf(-v0)); v1 = v1 / (1.f + expf(-v1));
                v2 = v2 / (1.f + expf(-v2)); v3 = v3 / (1.f + expf(-v3));
            }
            float2 p0 = make_float2(v0, v1), p1 = make_float2(v2, v3);
            *(float2*)&Cmat[(size_t)r0 * C_ + cc] = p0;
            *(float2*)&Cmat[(size_t)(r0 + 8) * C_ + cc] = p1;
        }
    }
}

// ============ wkv phase 1: per (b,h,chunk) — chunk-local terms + state increment ============
// grid 4096 = bh*32+ck; 256 threads; dynamic smem 6 tiles.
__global__ void wkv_p1(const float* __restrict__ wkvstate,
                       const float* __restrict__ time_decay,
                       const float* __restrict__ time_faaaa)
{
    extern __shared__ float sm[];
    float (*Rs)[PCH] = (float (*)[PCH])(sm);
    float (*Ks)[PCH] = (float (*)[PCH])(sm + 1 * 64 * PCH);
    float (*Vs)[PCH] = (float (*)[PCH])(sm + 2 * 64 * PCH);
    float (*Am)[PCH] = (float (*)[PCH])(sm + 3 * 64 * PCH);
    float (*WF)[PCH] = (float (*)[PCH])(sm + 4 * 64 * PCH);
    float (*Ws)[PCH] = (float (*)[PCH])(sm + 5 * 64 * PCH);
    __shared__ float ew[64], uu[64], bonus[64];

    const int gid = blockIdx.x;
    const int bh = gid >> 5, ck = gid & 31;
    const int b = bh >> 5, h = bh & 31;
    const int tid = threadIdx.x;
    const int row = tid & 63, jg = tid >> 6, j0 = jg * 16;

    if (tid < 64) {
        ew[tid] = expf(time_decay[h * 64 + tid]);
        uu[tid] = time_faaaa[h * 64 + tid];
    }
    const float* W0 = wkvstate + h * 64 * 64;
#pragma unroll
    for (int j = 0; j < 16; j++) Ws[row][j0 + j] = W0[row * 64 + j0 + j];

    const int t0 = ck * 64;
    const int off = (b * T_) * C_ + h * 64 + (t0 + row) * C_ + j0;
#pragma unroll
    for (int j4 = 0; j4 < 4; j4++) {
        float4 r4 = *(const float4*)&g_r[off + 4 * j4];
        float4 k4 = *(const float4*)&g_k[off + 4 * j4];
        float4 v4 = *(const float4*)&g_v[off + 4 * j4];
        int jj = j0 + 4 * j4;
        Rs[row][jj + 0] = r4.x; Rs[row][jj + 1] = r4.y; Rs[row][jj + 2] = r4.z; Rs[row][jj + 3] = r4.w;
        Ks[row][jj + 0] = k4.x; Ks[row][jj + 1] = k4.y; Ks[row][jj + 2] = k4.z; Ks[row][jj + 3] = k4.w;
        Vs[row][jj + 0] = v4.x; Vs[row][jj + 1] = v4.y; Vs[row][jj + 2] = v4.z; Vs[row][jj + 3] = v4.w;
    }
    __syncthreads();

    // WF = r * w^t_global
    {
        float tg = (float)(t0 + row);
#pragma unroll
        for (int j = 0; j < 16; j++)
            WF[row][j0 + j] = Rs[row][j0 + j] * expf(-tg * ew[j0 + j]);
    }
    // bonus with raw K
    if (tid < 64) {
        float s = 0.f;
        for (int kk = 0; kk < 64; kk++) s += Rs[tid][kk] * Ks[tid][kk] * uu[kk];
        bonus[tid] = s;
    }
    __syncthreads();

    // K2 = k * w^(T-1-q)
    {
        float qb = (float)(T_ - 1 - (t0 + row));
#pragma unroll
        for (int j = 0; j < 16; j++)
            Ks[row][j0 + j] *= expf(-qb * ew[j0 + j]);
    }
    __syncthreads();

    // G = K2^T V  (row = k-index)  -> g_S
    {
        float ga[16];
#pragma unroll
        for (int j = 0; j < 16; j++) ga[j] = 0.f;
        for (int q = 0; q < 64; q++) {
            float kv = Ks[q][row];
#pragma unroll
            for (int j = 0; j < 16; j++) ga[j] += kv * Vs[q][j0 + j];
        }
        float* gp = g_S + (size_t)gid * 4096 + row * 64 + j0;
#pragma unroll
        for (int j = 0; j < 16; j++) gp[j] = ga[j];
    }

    // A = R K2^T, strict lower mask
    {
        float a[16];
#pragma unroll
        for (int j = 0; j < 16; j++) a[j] = 0.f;
        for (int kk = 0; kk < 64; kk++) {
            float rv = Rs[row][kk];
#pragma unroll
            for (int j = 0; j < 16; j++) a[j] += rv * Ks[j0 + j][kk];
        }
#pragma unroll
        for (int j = 0; j < 16; j++)
            Am[row][j0 + j] = (j0 + j < row) ? a[j] : 0.f;
    }
    __syncthreads();

    // P = A V + bonus*v + WF @ W0  -> g_po
    {
        float o[16];
#pragma unroll
        for (int j = 0; j < 16; j++) o[j] = 0.f;
        for (int q = 0; q < 64; q++) {
            float av = Am[row][q];
#pragma unroll
            for (int j = 0; j < 16; j++) o[j] += av * Vs[q][j0 + j];
        }
        float bb = bonus[row];
#pragma unroll
        for (int j = 0; j < 16; j++) o[j] += bb * Vs[row][j0 + j];
        for (int kk = 0; kk < 64; kk++) {
            float rw = WF[row][kk];
#pragma unroll
            for (int j = 0; j < 16; j++) o[j] += rw * Ws[kk][j0 + j];
        }
        float* pp = g_po + (size_t)gid * 4096 + row * 64 + j0;
#pragma unroll
        for (int j = 0; j < 16; j++) pp[j] = o[j];
    }
}

// ============ wkv phase 2: exclusive prefix of G over chunks (per bh) ============
__global__ void wkv_p2()
{
    const int bh = blockIdx.x;
    const int e = threadIdx.x * 16;
    float run[16];
#pragma unroll
    for (int j = 0; j < 16; j++) run[j] = 0.f;
    for (int ck = 0; ck < 32; ck++) {
        float* p = g_S + (size_t)(bh * 32 + ck) * 4096 + e;
        float t[16];
#pragma unroll
        for (int j4 = 0; j4 < 4; j4++) {
            float4 v = *(const float4*)&p[4 * j4];
            t[4 * j4] = v.x; t[4 * j4 + 1] = v.y; t[4 * j4 + 2] = v.z; t[4 * j4 + 3] = v.w;
        }
#pragma unroll
        for (int j4 = 0; j4 < 4; j4++) {
            float4 v = make_float4(run[4 * j4], run[4 * j4 + 1], run[4 * j4 + 2], run[4 * j4 + 3]);
            *(float4*)&p[4 * j4] = v;
        }
#pragma unroll
        for (int j = 0; j < 16; j++) run[j] += t[j];
    }
}

// ============ wkv phase 3: o = P + R@S_c, then bf16-cast + groupnorm + gate ============
__global__ void wkv_p3(const float* __restrict__ lnw, const float* __restrict__ lnb)
{
    extern __shared__ float sm[];
    float (*Rs)[PCH] = (float (*)[PCH])(sm);
    float (*Ss)[PCH] = (float (*)[PCH])(sm + 1 * 64 * PCH);
    float (*Am)[PCH] = (float (*)[PCH])(sm + 2 * 64 * PCH);
    __shared__ float mu_s[64], rstd_s[64], lw_s[64], lb_s[64];

    const int gid = blockIdx.x;
    const int bh = gid >> 5, ck = gid & 31;
    const int b = bh >> 5, h = bh & 31;
    const int tid = threadIdx.x;
    const int row = tid & 63, jg = tid >> 6, j0 = jg * 16;

    if (tid < 64) {
        lw_s[tid] = lnw[h * 64 + tid];
        lb_s[tid] = lnb[h * 64 + tid];
    }
    const int t0 = ck * 64;
    const int off = (b * T_) * C_ + h * 64 + (t0 + row) * C_ + j0;

#pragma unroll
    for (int j4 = 0; j4 < 4; j4++) {
        float4 r4 = *(const float4*)&g_r[off + 4 * j4];
        int jj = j0 + 4 * j4;
        Rs[row][jj + 0] = r4.x; Rs[row][jj + 1] = r4.y; Rs[row][jj + 2] = r4.z; Rs[row][jj + 3] = r4.w;
        float4 s4 = *(const float4*)&g_S[(size_t)gid * 4096 + row * 64 + jj];
        Ss[row][jj + 0] = s4.x; Ss[row][jj + 1] = s4.y; Ss[row][jj + 2] = s4.z; Ss[row][jj + 3] = s4.w;
    }
    float o[16];
    {
        const float* pp = g_po + (size_t)gid * 4096 + row * 64 + j0;
#pragma unroll
        for (int j = 0; j < 16; j++) o[j] = pp[j];
    }
    __syncthreads();

    for (int kk = 0; kk < 64; kk++) {
        float rv = Rs[row][kk];
#pragma unroll
        for (int j = 0; j < 16; j++) o[j] += rv * Ss[kk][j0 + j];
    }

#pragma unroll
    for (int j = 0; j < 16; j++)
        Am[row][j0 + j] = __bfloat162float(__float2bfloat16(o[j]));
    __syncthreads();

    if (tid < 64) {
        float m = 0.f;
        for (int j = 0; j < 64; j++) m += Am[tid][j];
        m *= (1.f / 64.f);
        float v2 = 0.f;
        for (int j = 0; j < 64; j++) { float d = Am[tid][j] - m; v2 += d * d; }
        v2 *= (1.f / 64.f);
        mu_s[tid] = m;
        rstd_s[tid] = 1.f / sqrtf(v2 + EPS_);
    }
    __syncthreads();

    {
        float m = mu_s[row], rs = rstd_s[row];
#pragma unroll
        for (int j = 0; j < 16; j++) {
            float y = (Am[row][j0 + j] - m) * rs * lw_s[j0 + j] + lb_s[j0 + j];
            float z = y * g_gt[off + j];
            __nv_bfloat16 hh = __float2bfloat16(z);
            g_zh[off + j] = hh;
            g_zl[off + j] = __float2bfloat16(z - __bfloat162float(hh));
        }
    }
}

// ---------------- launch ----------------
extern "C" void kernel_launch(void* const* d_in, const int* in_sizes, int n_in,
                              void* d_out, int out_size)
{
    const float* x     = (const float*)d_in[0];
    const float* state = (const float*)d_in[1];
    const float* wkvs  = (const float*)d_in[2];
    const float* tmk   = (const float*)d_in[3];
    const float* tmv   = (const float*)d_in[4];
    const float* tmr   = (const float*)d_in[5];
    const float* tmg   = (const float*)d_in[6];
    const float* tdec  = (const float*)d_in[7];
    const float* tfaa  = (const float*)d_in[8];
    const float* w_r   = (const float*)d_in[9];
    const float* w_k   = (const float*)d_in[10];
    const float* w_v   = (const float*)d_in[11];
    const float* w_g   = (const float*)d_in[12];
    const float* w_o   = (const float*)d_in[13];
    const float* lnw   = (const float*)d_in[14];
    const float* lnb   = (const float*)d_in[15];

    __nv_bfloat16 *xrh,*xrl,*xkh,*xkl,*xvh,*xvl,*xgh,*xgl,*zh,*zl;
    __nv_bfloat16 *wrh,*wrl,*wkh,*wkl,*wvh,*wvl,*wgh,*wgl,*woh,*wol;
    float *pr,*pk,*pv,*pg;
    cudaGetSymbolAddress((void**)&xrh, g_xrh); cudaGetSymbolAddress((void**)&xrl, g_xrl);
    cudaGetSymbolAddress((void**)&xkh, g_xkh); cudaGetSymbolAddress((void**)&xkl, g_xkl);
    cudaGetSymbolAddress((void**)&xvh, g_xvh); cudaGetSymbolAddress((void**)&xvl, g_xvl);
    cudaGetSymbolAddress((void**)&xgh, g_xgh); cudaGetSymbolAddress((void**)&xgl, g_xgl);
    cudaGetSymbolAddress((void**)&zh,  g_zh);  cudaGetSymbolAddress((void**)&zl,  g_zl);
    cudaGetSymbolAddress((void**)&wrh, g_wrh); cudaGetSymbolAddress((void**)&wrl, g_wrl);
    cudaGetSymbolAddress((void**)&wkh, g_wkh); cudaGetSymbolAddress((void**)&wkl, g_wkl);
    cudaGetSymbolAddress((void**)&wvh, g_wvh); cudaGetSymbolAddress((void**)&wvl, g_wvl);
    cudaGetSymbolAddress((void**)&wgh, g_wgh); cudaGetSymbolAddress((void**)&wgl, g_wgl);
    cudaGetSymbolAddress((void**)&woh, g_woh); cudaGetSymbolAddress((void**)&wol, g_wol);
    cudaGetSymbolAddress((void**)&pr,  g_r);   cudaGetSymbolAddress((void**)&pk,  g_k);
    cudaGetSymbolAddress((void**)&pv,  g_v);   cudaGetSymbolAddress((void**)&pg,  g_gt);

    mix_kernel<<<(NTOT + 255) / 256, 256>>>(x, state, tmk, tmv, tmr, tmg);
    int wg = (WSZ + 255) / 256;
    wconv_kernel<<<wg, 256>>>(w_r, wrh, wrl);
    wconv_kernel<<<wg, 256>>>(w_k, wkh, wkl);
    wconv_kernel<<<wg, 256>>>(w_v, wvh, wvl);
    wconv_kernel<<<wg, 256>>>(w_g, wgh, wgl);
    wconv_kernel<<<wg, 256>>>(w_o, woh, wol);

    const int gsm = NSTAGE * STG_BYTES;  // 192KB
    cudaFuncSetAttribute(hgemm_nt<0>, cudaFuncAttributeMaxDynamicSharedMemorySize, gsm);
    cudaFuncSetAttribute(hgemm_nt<1>, cudaFuncAttributeMaxDynamicSharedMemorySize, gsm);

    dim3 gg(C_ / 128, M_ / 128);
    hgemm_nt<0><<<gg, 256, gsm>>>(xrh, xrl, wrh, wrl, pr);
    hgemm_nt<0><<<gg, 256, gsm>>>(xkh, xkl, wkh, wkl, pk);
    hgemm_nt<0><<<gg, 256, gsm>>>(xvh, xvl, wvh, wvl, pv);
    hgemm_nt<1><<<gg, 256, gsm>>>(xgh, xgl, wgh, wgl, pg);

    const int p1sm = 6 * 64 * PCH * 4;
    const int p3sm = 3 * 64 * PCH * 4;
    cudaFuncSetAttribute(wkv_p1, cudaFuncAttributeMaxDynamicSharedMemorySize, p1sm);
    cudaFuncSetAttribute(wkv_p3, cudaFuncAttributeMaxDynamicSharedMemorySize, p3sm);
    wkv_p1<<<128 * 32, 256, p1sm>>>(wkvs, tdec, tfaa);
    wkv_p2<<<128, 256>>>();
    wkv_p3<<<128 * 32, 256, p3sm>>>(lnw, lnb);

    hgemm_nt<0><<<gg, 256, gsm>>>(zh, zl, woh, wol, (float*)d_out);
}